// round 15
// baseline (speedup 1.0000x reference)
#include <cuda_runtime.h>
#include <cuda_fp16.h>
#include <math.h>
#include <stdint.h>

// Problem constants
#define BATCH 2
#define SEQ   2048
#define ROWS  (BATCH * SEQ)        // 4096
#define INNER 512
#define HEADS 8
#define DHEAD 64
#define QKV_N (3 * INNER)          // 1536
#define FF_N  (4 * INNER)          // 2048
#define LN_EPS 1e-6f

// exp folding: P = exp((S - m) * 0.125) = ex2((S - m) * CL)
#define CL 0.18033688011112042f    // 0.125 * log2(e)

// ---------------------------------------------------------------------------
// Scratch
// ---------------------------------------------------------------------------
__device__ float g_proj [ROWS * INNER];
__device__ float g_projB[ROWS * INNER];
__device__ float g_res1 [ROWS * INNER];
__device__ float g_ff   [ROWS * INNER];
__device__ float g_ffB  [ROWS * INNER];

__device__ __half g_ah [ROWS * FF_N];    // activations (x / attn / res1)
__device__ __half g_ah2[ROWS * FF_N];    // qkv / mid
__device__ __half g_bh [FF_N * INNER];   // w_ff1
__device__ __half g_bh2[FF_N * INNER];   // w_ff2
__device__ __half g_wq [INNER * QKV_N];  // w_qkv
__device__ __half g_wo [INNER * INNER];  // w_out

// ---------------------------------------------------------------------------
// PTX helpers
// ---------------------------------------------------------------------------
__device__ __forceinline__ void ldsm_x4(uint32_t& r0, uint32_t& r1,
                                        uint32_t& r2, uint32_t& r3, uint32_t addr)
{
    asm volatile("ldmatrix.sync.aligned.m8n8.x4.shared.b16 {%0,%1,%2,%3}, [%4];"
                 : "=r"(r0), "=r"(r1), "=r"(r2), "=r"(r3) : "r"(addr));
}
__device__ __forceinline__ void ldsm_x2t(uint32_t& r0, uint32_t& r1, uint32_t addr)
{
    asm volatile("ldmatrix.sync.aligned.m8n8.x2.trans.shared.b16 {%0,%1}, [%2];"
                 : "=r"(r0), "=r"(r1) : "r"(addr));
}
__device__ __forceinline__ void mma_f16(float* c, const uint32_t* a, const uint32_t* b)
{
    asm volatile(
        "mma.sync.aligned.m16n8k16.row.col.f32.f16.f16.f32 "
        "{%0,%1,%2,%3}, {%4,%5,%6,%7}, {%8,%9}, {%0,%1,%2,%3};"
        : "+f"(c[0]), "+f"(c[1]), "+f"(c[2]), "+f"(c[3])
        : "r"(a[0]), "r"(a[1]), "r"(a[2]), "r"(a[3]), "r"(b[0]), "r"(b[1]));
}
__device__ __forceinline__ void mma_f16acc(uint32_t& c0, uint32_t& c1,
                                           const uint32_t* a, const uint32_t* b)
{
    asm volatile(
        "mma.sync.aligned.m16n8k16.row.col.f16.f16.f16.f16 "
        "{%0,%1}, {%2,%3,%4,%5}, {%6,%7}, {%0,%1};"
        : "+r"(c0), "+r"(c1)
        : "r"(a[0]), "r"(a[1]), "r"(a[2]), "r"(a[3]), "r"(b[0]), "r"(b[1]));
}
__device__ __forceinline__ uint32_t packh2(float a, float b)
{
    __half2 t = __floats2half2_rn(a, b);
    return *reinterpret_cast<uint32_t*>(&t);
}
__device__ __forceinline__ void cp_async16(uint32_t dst, const void* src)
{
    asm volatile("cp.async.cg.shared.global [%0], [%1], 16;"
                 :: "r"(dst), "l"(src));
}
__device__ __forceinline__ float ex2(float x)
{
    float y;
    asm("ex2.approx.f32 %0, %1;" : "=f"(y) : "f"(x));
    return y;
}
__device__ __forceinline__ __half2 h2ex2(__half2 x)
{
    uint32_t xi = *reinterpret_cast<uint32_t*>(&x);
    uint32_t yi;
    asm("ex2.approx.f16x2 %0, %1;" : "=r"(yi) : "r"(xi));
    return *reinterpret_cast<__half2*>(&yi);
}

// ---------------------------------------------------------------------------
// fp32 -> fp16 conversions (fused multi-array)
// ---------------------------------------------------------------------------
__device__ __forceinline__ uint2 h4_of(float4 v)
{
    union { __half2 h[2]; uint2 u; } H;
    H.h[0] = __floats2half2_rn(v.x, v.y);
    H.h[1] = __floats2half2_rn(v.z, v.w);
    return H.u;
}

__global__ __launch_bounds__(256) void cvt_h3_kernel(
    const float4* __restrict__ x0, uint2* __restrict__ h0, int n0,
    const float4* __restrict__ x1, uint2* __restrict__ h1, int n1,
    const float4* __restrict__ x2, uint2* __restrict__ h2, int n2)
{
    int i = blockIdx.x * blockDim.x + threadIdx.x;
    if (i < n0)                { h0[i]           = h4_of(x0[i]); }
    else if (i < n0 + n1)      { h1[i - n0]      = h4_of(x1[i - n0]); }
    else if (i < n0 + n1 + n2) { h2[i - n0 - n1] = h4_of(x2[i - n0 - n1]); }
}

__global__ __launch_bounds__(256) void cvt_h2_kernel(
    const float4* __restrict__ x0, uint2* __restrict__ h0, int n0,
    const float4* __restrict__ x1, uint2* __restrict__ h1, int n1)
{
    int i = blockIdx.x * blockDim.x + threadIdx.x;
    if (i < n0)           { h0[i]      = h4_of(x0[i]); }
    else if (i < n0 + n1) { h1[i - n0] = h4_of(x1[i - n0]); }
}

// ---------------------------------------------------------------------------
// Tensor-core fp16 GEMM (fp32 accum), 128x128xK, 256 threads, 3-stage pipe.
// gridDim.z == 2 -> split-K: z=0 writes C (+bias), z=1 writes C2.
// ---------------------------------------------------------------------------
__global__ __launch_bounds__(256) void hgemm_kernel(
    const __half* __restrict__ A, const __half* __restrict__ B,
    const float* __restrict__ bias, float* __restrict__ C, float* __restrict__ C2,
    __half* __restrict__ Ch,
    int M, int N, int Klen, int Ks)
{
    extern __shared__ uint4 smem[];
    uint4* sA = smem;            // [3][512]
    uint4* sB = smem + 3 * 512;  // [3][512]

    const int tid  = threadIdx.x;
    const int lane = tid & 31;
    const int warp = tid >> 5;
    const int wm   = warp >> 2;
    const int wn   = warp & 3;
    const int bm   = blockIdx.y * 128;
    const int bn   = blockIdx.x * 128;
    const int zz   = blockIdx.z;
    const int koff = zz * Klen;

    float* Cout = zz ? C2 : C;
    const bool doBias = (bias != nullptr) && (zz == 0);

    const int arow = tid >> 2;
    const int ach  = tid & 3;
    const int brow = tid >> 4;
    const int bch  = tid & 15;

    const int aSwS = ach ^ ((arow >> 1) & 3);
    const int bSwS = bch ^ (brow & 7);

    const uint32_t aBase = (uint32_t)__cvta_generic_to_shared(sA);
    const uint32_t bBase = (uint32_t)__cvta_generic_to_shared(sB);
    const int ar   = wm * 64 + (lane & 15);
    const int aSw  = (ar >> 1) & 3;
    const int aHi  = lane >> 4;
    const int br   = lane & 15;
    const int bSw  = br & 7;

    const int sa0 = arow * 4 + aSwS;
    const int sa1 = (arow + 64) * 4 + aSwS;
    const int sb0 = brow * 16 + bSwS;
    const int sb1 = (brow + 16) * 16 + bSwS;

    float acc[4][4][4];
#pragma unroll
    for (int i = 0; i < 4; i++)
#pragma unroll
        for (int j = 0; j < 4; j++)
#pragma unroll
            for (int r = 0; r < 4; r++) acc[i][j][r] = 0.f;

    auto fill = [&](int kk, int st) {
        uint32_t a0 = aBase + (uint32_t)(st * 8192);
        uint32_t b0 = bBase + (uint32_t)(st * 8192);
        cp_async16(a0 + sa0 * 16, A + (size_t)(bm + arow)      * Ks + koff + kk + ach * 8);
        cp_async16(a0 + sa1 * 16, A + (size_t)(bm + arow + 64) * Ks + koff + kk + ach * 8);
        cp_async16(b0 + sb0 * 16, B + (size_t)(koff + kk + brow)      * N + bn + bch * 8);
        cp_async16(b0 + sb1 * 16, B + (size_t)(koff + kk + brow + 16) * N + bn + bch * 8);
        asm volatile("cp.async.commit_group;");
    };

    const int nIter = Klen / 32;
    fill(0, 0);
    fill(32, 1);

    for (int it = 0; it < nIter; it++) {
        const int st = it % 3;
        if (it + 1 < nIter) {
            asm volatile("cp.async.wait_group 1;");
        } else {
            asm volatile("cp.async.wait_group 0;");
        }
        __syncthreads();
        if (it + 2 < nIter) fill((it + 2) * 32, (it + 2) % 3);

#pragma unroll
        for (int s = 0; s < 2; s++) {
            uint32_t Af[4][4];
            uint32_t Bf[4][2];
#pragma unroll
            for (int i = 0; i < 4; i++) {
                uint32_t addr = aBase + (uint32_t)(st * 8192 +
                    (ar + i * 16) * 64 + (((2 * s + aHi) ^ aSw) * 16));
                ldsm_x4(Af[i][0], Af[i][1], Af[i][2], Af[i][3], addr);
            }
#pragma unroll
            for (int j = 0; j < 4; j++) {
                uint32_t addr = bBase + (uint32_t)(st * 8192 +
                    (s * 16 + br) * 256 + ((((wn << 2) + j) ^ bSw) * 16));
                ldsm_x2t(Bf[j][0], Bf[j][1], addr);
            }
#pragma unroll
            for (int i = 0; i < 4; i++)
#pragma unroll
                for (int j = 0; j < 4; j++)
                    mma_f16(acc[i][j], Af[i], Bf[j]);
        }
    }

    const int grp = lane >> 2;
    const int qc  = (lane & 3) * 2;
#pragma unroll
    for (int i = 0; i < 4; i++) {
#pragma unroll
        for (int j = 0; j < 4; j++) {
            int row = bm + wm * 64 + i * 16 + grp;
            int col = bn + wn * 32 + j * 8 + qc;
            float b0 = 0.f, b1 = 0.f;
            if (doBias) { b0 = bias[col]; b1 = bias[col + 1]; }
            float v00 = acc[i][j][0] + b0, v01 = acc[i][j][1] + b1;
            float v10 = acc[i][j][2] + b0, v11 = acc[i][j][3] + b1;
            if (Cout) {
                *(float2*)(Cout + (size_t)row * N + col)       = make_float2(v00, v01);
                *(float2*)(Cout + (size_t)(row + 8) * N + col) = make_float2(v10, v11);
            }
            if (Ch) {
                *(uint32_t*)(Ch + (size_t)row * N + col)       = packh2(v00, v01);
                *(uint32_t*)(Ch + (size_t)(row + 8) * N + col) = packh2(v10, v11);
            }
        }
    }
}

// ---------------------------------------------------------------------------
// Flash attention, fp16 accumulators, KB=128 key block (halves the number of
// serial softmax chains). 128 q-rows/CTA (32/warp), 2-stage cp.async pipeline,
// 64 KB dynamic smem.
// ---------------------------------------------------------------------------
__global__ __launch_bounds__(128) void attn_mma_kernel(
    const __half* __restrict__ qh, __half* __restrict__ outH)
{
    extern __shared__ uint4 asmem[];
    uint4* sK = asmem;            // [2][1024]
    uint4* sV = asmem + 2048;     // [2][1024]

    const int tid  = threadIdx.x;
    const int lane = tid & 31;
    const int warp = tid >> 5;
    const int g    = lane >> 2;
    const int t    = lane & 3;
    const int b    = blockIdx.y >> 3;
    const int h    = blockIdx.y & 7;
    const int q0   = blockIdx.x * 128;

    uint32_t Qh[2][4][4];
#pragma unroll
    for (int u = 0; u < 2; u++) {
#pragma unroll
        for (int kt = 0; kt < 4; kt++) {
#pragma unroll
            for (int p = 0; p < 4; p++) {
                size_t row = (size_t)(b * SEQ + q0 + warp * 32 + u * 16 + g + (p & 1) * 8);
                int col = h * DHEAD + kt * 16 + (p >> 1) * 8 + 2 * t;
                Qh[u][kt][p] = *(const uint32_t*)(qh + row * QKV_N + col);
            }
        }
    }

    const uint32_t kBase = (uint32_t)__cvta_generic_to_shared(sK);
    const uint32_t vBase = (uint32_t)__cvta_generic_to_shared(sV);

    uint32_t O[2][8][2];
#pragma unroll
    for (int u = 0; u < 2; u++)
#pragma unroll
        for (int j = 0; j < 8; j++) { O[u][j][0] = 0u; O[u][j][1] = 0u; }
    float m[2][2], l[2][2];
#pragma unroll
    for (int u = 0; u < 2; u++) { m[u][0] = m[u][1] = -1e30f; l[u][0] = l[u][1] = 0.f; }

    const __half2 CL2 = __float2half2_rn(CL);

    const int kRowOff = (lane & 7) + ((lane >> 4) << 3);
    const int kHalf   = (lane >> 3) & 1;
    const int vRowOff = lane & 15;

    // fill map: 1 thread per row (128 rows), 8 uint4 K + 8 uint4 V
    const int fr  = tid;
    const int fsw = fr & 7;

    auto fill = [&](int kb, int stage) {
        size_t rowoff = (size_t)(b * SEQ + kb * 128 + fr) * QKV_N + h * DHEAD;
        const __half* kr = qh + rowoff + INNER;
        const __half* vr = qh + rowoff + 2 * INNER;
#pragma unroll
        for (int c = 0; c < 8; c++) {
            int cc = c ^ fsw;
            uint32_t off = (uint32_t)((stage * 1024 + fr * 8 + cc) * 16);
            cp_async16(kBase + off, kr + c * 8);
            cp_async16(vBase + off, vr + c * 8);
        }
        asm volatile("cp.async.commit_group;");
    };

    constexpr int NB = SEQ / 128;   // 16 iterations
    fill(0, 0);

    for (int kb = 0; kb < NB; kb++) {
        const int stage = kb & 1;
        if (kb + 1 < NB) {
            fill(kb + 1, stage ^ 1);
            asm volatile("cp.async.wait_group 1;");
        } else {
            asm volatile("cp.async.wait_group 0;");
        }
        __syncthreads();

        // ---- S = QK^T over 128 keys, fp16 accumulate ----
        uint32_t S[2][16][2];
#pragma unroll
        for (int u = 0; u < 2; u++)
#pragma unroll
            for (int j = 0; j < 16; j++) { S[u][j][0] = 0u; S[u][j][1] = 0u; }

#pragma unroll
        for (int kt = 0; kt < 4; kt++) {
            uint32_t Bh[16][2];
#pragma unroll
            for (int jp = 0; jp < 8; jp++) {
                int row = jp * 16 + kRowOff;
                uint32_t off = (uint32_t)((stage * 1024 + row * 8 +
                                           ((2 * kt + kHalf) ^ (row & 7))) * 16);
                ldsm_x4(Bh[2 * jp][0], Bh[2 * jp][1], Bh[2 * jp + 1][0], Bh[2 * jp + 1][1],
                        kBase + off);
            }
#pragma unroll
            for (int j = 0; j < 16; j++) {
                mma_f16acc(S[0][j][0], S[0][j][1], Qh[0][kt], Bh[j]);
                mma_f16acc(S[1][j][0], S[1][j][1], Qh[1][kt], Bh[j]);
            }
        }

        // ---- h2 online softmax (one chain per 128 keys) ----
#pragma unroll
        for (int u = 0; u < 2; u++) {
            __half2 mh0 = __float2half2_rn(-60000.f);
            __half2 mh1 = mh0;
#pragma unroll
            for (int j = 0; j < 16; j++) {
                mh0 = __hmax2(mh0, *reinterpret_cast<__half2*>(&S[u][j][0]));
                mh1 = __hmax2(mh1, *reinterpret_cast<__half2*>(&S[u][j][1]));
            }
            float mx0 = fmaxf(__low2float(mh0), __high2float(mh0));
            float mx1 = fmaxf(__low2float(mh1), __high2float(mh1));
            mx0 = fmaxf(mx0, __shfl_xor_sync(0xffffffffu, mx0, 1));
            mx0 = fmaxf(mx0, __shfl_xor_sync(0xffffffffu, mx0, 2));
            mx1 = fmaxf(mx1, __shfl_xor_sync(0xffffffffu, mx1, 1));
            mx1 = fmaxf(mx1, __shfl_xor_sync(0xffffffffu, mx1, 2));
            float mn0 = fmaxf(m[u][0], mx0);
            float mn1 = fmaxf(m[u][1], mx1);
            float a0 = ex2((m[u][0] - mn0) * CL);
            float a1 = ex2((m[u][1] - mn1) * CL);
            m[u][0] = mn0; m[u][1] = mn1;

            __half2 nm0 = __float2half2_rn(mn0);
            __half2 nm1 = __float2half2_rn(mn1);
            __half2 sum0 = __float2half2_rn(0.f);
            __half2 sum1 = sum0;
#pragma unroll
            for (int j = 0; j < 16; j++) {
                __half2 s0 = *reinterpret_cast<__half2*>(&S[u][j][0]);
                __half2 s1 = *reinterpret_cast<__half2*>(&S[u][j][1]);
                __half2 e0 = h2ex2(__hmul2(__hsub2(s0, nm0), CL2));
                __half2 e1 = h2ex2(__hmul2(__hsub2(s1, nm1), CL2));
                *reinterpret_cast<__half2*>(&S[u][j][0]) = e0;
                *reinterpret_cast<__half2*>(&S[u][j][1]) = e1;
                sum0 = __hadd2(sum0, e0);
                sum1 = __hadd2(sum1, e1);
            }
            float s0 = __low2float(sum0) + __high2float(sum0);
            float s1 = __low2float(sum1) + __high2float(sum1);
            s0 += __shfl_xor_sync(0xffffffffu, s0, 1);
            s0 += __shfl_xor_sync(0xffffffffu, s0, 2);
            s1 += __shfl_xor_sync(0xffffffffu, s1, 1);
            s1 += __shfl_xor_sync(0xffffffffu, s1, 2);
            l[u][0] = l[u][0] * a0 + s0;
            l[u][1] = l[u][1] * a1 + s1;

            __half2 a0h = __float2half2_rn(a0);
            __half2 a1h = __float2half2_rn(a1);
#pragma unroll
            for (int j = 0; j < 8; j++) {
                __half2 o0 = *reinterpret_cast<__half2*>(&O[u][j][0]);
                __half2 o1 = *reinterpret_cast<__half2*>(&O[u][j][1]);
                o0 = __hmul2(o0, a0h);
                o1 = __hmul2(o1, a1h);
                *reinterpret_cast<__half2*>(&O[u][j][0]) = o0;
                *reinterpret_cast<__half2*>(&O[u][j][1]) = o1;
            }
        }

        // ---- O += P @ V over 128 keys ----
#pragma unroll
        for (int kt = 0; kt < 8; kt++) {
            uint32_t Vb[8][2];
#pragma unroll
            for (int j = 0; j < 8; j++) {
                int row = kt * 16 + vRowOff;
                uint32_t off = (uint32_t)((stage * 1024 + row * 8 + (j ^ (row & 7))) * 16);
                ldsm_x2t(Vb[j][0], Vb[j][1], vBase + off);
            }
            uint32_t Pa0[4] = { S[0][2 * kt][0], S[0][2 * kt][1],
                                S[0][2 * kt + 1][0], S[0][2 * kt + 1][1] };
            uint32_t Pa1[4] = { S[1][2 * kt][0], S[1][2 * kt][1],
                                S[1][2 * kt + 1][0], S[1][2 * kt + 1][1] };
#pragma unroll
            for (int j = 0; j < 8; j++) {
                mma_f16acc(O[0][j][0], O[0][j][1], Pa0, Vb[j]);
                mma_f16acc(O[1][j][0], O[1][j][1], Pa1, Vb[j]);
            }
        }
        __syncthreads();
    }

    // ---- epilogue: normalize (h2), store fp16 ----
#pragma unroll
    for (int u = 0; u < 2; u++) {
        __half2 il0 = __float2half2_rn(1.f / l[u][0]);
        __half2 il1 = __float2half2_rn(1.f / l[u][1]);
        int row0 = b * SEQ + q0 + warp * 32 + u * 16 + g;
#pragma unroll
        for (int j = 0; j < 8; j++) {
            int col = h * DHEAD + j * 8 + 2 * t;
            __half2 o0 = __hmul2(*reinterpret_cast<__half2*>(&O[u][j][0]), il0);
            __half2 o1 = __hmul2(*reinterpret_cast<__half2*>(&O[u][j][1]), il1);
            *(__half2*)(outH + (size_t)row0 * INNER + col)       = o0;
            *(__half2*)(outH + (size_t)(row0 + 8) * INNER + col) = o1;
        }
    }
}

// ---------------------------------------------------------------------------
// Fused residual + LayerNorm: out = LN(A + B (+ B2)) (+ optional fp16 out)
// ---------------------------------------------------------------------------
__global__ __launch_bounds__(128) void ln_res_kernel(
    const float* __restrict__ A, const float* __restrict__ B,
    const float* __restrict__ B2,
    const float* __restrict__ g, const float* __restrict__ be,
    float* __restrict__ out, __half* __restrict__ outH)
{
    const int row = blockIdx.x;
    const int tid = threadIdx.x;
    const size_t off = (size_t)row * INNER + tid * 4;

    float4 va = *(const float4*)(A + off);
    float4 vb = *(const float4*)(B + off);
    float x0 = va.x + vb.x, x1 = va.y + vb.y, x2 = va.z + vb.z, x3 = va.w + vb.w;
    if (B2) {
        float4 vc = *(const float4*)(B2 + off);
        x0 += vc.x; x1 += vc.y; x2 += vc.z; x3 += vc.w;
    }

    float s  = x0 + x1 + x2 + x3;
    float s2 = x0 * x0 + x1 * x1 + x2 * x2 + x3 * x3;
#pragma unroll
    for (int o2 = 16; o2 >= 1; o2 >>= 1) {
        s  += __shfl_xor_sync(0xffffffffu, s,  o2);
        s2 += __shfl_xor_sync(0xffffffffu, s2, o2);
    }
    __shared__ float sh[8];
    int w = tid >> 5;
    if ((tid & 31) == 0) { sh[w] = s; sh[4 + w] = s2; }
    __syncthreads();
    s  = sh[0] + sh[1] + sh[2] + sh[3];
    s2 = sh[4] + sh[5] + sh[6] + sh[7];

    const float inv_n = 1.f / (float)INNER;
    float mu   = s * inv_n;
    float var  = s2 * inv_n - mu * mu;
    float rstd = rsqrtf(var + LN_EPS);

    float4 vg  = *(const float4*)(g  + tid * 4);
    float4 vbe = *(const float4*)(be + tid * 4);
    float4 vo;
    vo.x = (x0 - mu) * rstd * vg.x + vbe.x;
    vo.y = (x1 - mu) * rstd * vg.y + vbe.y;
    vo.z = (x2 - mu) * rstd * vg.z + vbe.z;
    vo.w = (x3 - mu) * rstd * vg.w + vbe.w;
    *(float4*)(out + off) = vo;

    if (outH) {
        *(uint2*)(outH + off) = make_uint2(packh2(vo.x, vo.y), packh2(vo.z, vo.w));
    }
}

// ---------------------------------------------------------------------------
// Launch
// ---------------------------------------------------------------------------
#define GEMM_SMEM 49152
#define ATTN_SMEM 65536

extern "C" void kernel_launch(void* const* d_in, const int* in_sizes, int n_in,
                              void* d_out, int out_size)
{
    const float* x     = (const float*)d_in[0];
    const float* w_qkv = (const float*)d_in[1];
    const float* w_out = (const float*)d_in[2];
    const float* b_out = (const float*)d_in[3];
    const float* w_ff1 = (const float*)d_in[4];
    const float* w_ff2 = (const float*)d_in[5];
    const float* g1    = (const float*)d_in[6];
    const float* be1   = (const float*)d_in[7];
    const float* g2    = (const float*)d_in[8];
    const float* be2   = (const float*)d_in[9];
    float* out = (float*)d_out;

    float *proj, *projB, *res1, *ff, *ffB;
    __half *ah, *ah2, *bh, *bh2, *wq, *wo;
    cudaGetSymbolAddress((void**)&proj,  g_proj);
    cudaGetSymbolAddress((void**)&projB, g_projB);
    cudaGetSymbolAddress((void**)&res1,  g_res1);
    cudaGetSymbolAddress((void**)&ff,    g_ff);
    cudaGetSymbolAddress((void**)&ffB,   g_ffB);
    cudaGetSymbolAddress((void**)&ah,    g_ah);
    cudaGetSymbolAddress((void**)&ah2,   g_ah2);
    cudaGetSymbolAddress((void**)&bh,    g_bh);
    cudaGetSymbolAddress((void**)&bh2,   g_bh2);
    cudaGetSymbolAddress((void**)&wq,    g_wq);
    cudaGetSymbolAddress((void**)&wo,    g_wo);

    cudaFuncSetAttribute(hgemm_kernel,
                         cudaFuncAttributeMaxDynamicSharedMemorySize, GEMM_SMEM);
    cudaFuncSetAttribute(attn_mma_kernel,
                         cudaFuncAttributeMaxDynamicSharedMemorySize, ATTN_SMEM);

    // 0a) fp16 conversions: x -> ah, w_qkv -> wq, w_out -> wo
    {
        int n0 = ROWS * INNER / 4, n1 = INNER * QKV_N / 4, n2 = INNER * INNER / 4;
        int tot = n0 + n1 + n2;
        cvt_h3_kernel<<<(tot + 255) / 256, 256>>>(
            (const float4*)x, (uint2*)ah, n0,
            (const float4*)w_qkv, (uint2*)wq, n1,
            (const float4*)w_out, (uint2*)wo, n2);
    }
    // 0b) fp16 conversions: w_ff1 -> bh, w_ff2 -> bh2
    {
        int n0 = INNER * FF_N / 4, n1 = FF_N * INNER / 4;
        cvt_h2_kernel<<<(n0 + n1 + 255) / 256, 256>>>(
            (const float4*)w_ff1, (uint2*)bh, n0,
            (const float4*)w_ff2, (uint2*)bh2, n1);
    }

    // 1) qkv = x @ w_qkv  (fp16 -> fp16 out)
    hgemm_kernel<<<dim3(QKV_N / 128, ROWS / 128, 1), 256, GEMM_SMEM>>>(
        ah, wq, nullptr, nullptr, nullptr, ah2, ROWS, QKV_N, INNER, INNER);

    // 2) attention -> fp16 attn out (KB=128)
    attn_mma_kernel<<<dim3(SEQ / 128, BATCH * HEADS), 128, ATTN_SMEM>>>(ah2, ah);

    // 3) proj = attn @ w_out + b_out  (split-K=2 -> proj + projB, fp32)
    hgemm_kernel<<<dim3(INNER / 128, ROWS / 128, 2), 256, GEMM_SMEM>>>(
        ah, wo, b_out, proj, projB, nullptr, ROWS, INNER, INNER / 2, INNER);

    // 4) res1 = LN(x + proj + projB), emit fp16
    ln_res_kernel<<<ROWS, 128>>>(x, proj, projB, g1, be1, res1, ah);

    // 5) mid = res1 @ w_ff1 -> fp16
    hgemm_kernel<<<dim3(FF_N / 128, ROWS / 128, 1), 256, GEMM_SMEM>>>(
        ah, bh, nullptr, nullptr, nullptr, ah2, ROWS, FF_N, INNER, INNER);

    // 6) ff = mid @ w_ff2 (split-K=2 -> ff + ffB, fp32)
    hgemm_kernel<<<dim3(INNER / 128, ROWS / 128, 2), 256, GEMM_SMEM>>>(
        ah2, bh2, nullptr, ff, ffB, nullptr, ROWS, INNER, FF_N / 2, FF_N);

    // 7) out = LN(res1 + ff + ffB)
    ln_res_kernel<<<ROWS, 128>>>(res1, ff, ffB, g2, be2, out, nullptr);
}

// round 16
// speedup vs baseline: 1.0083x; 1.0083x over previous
#include <cuda_runtime.h>
#include <cuda_fp16.h>
#include <math.h>
#include <stdint.h>

// Problem constants
#define BATCH 2
#define SEQ   2048
#define ROWS  (BATCH * SEQ)        // 4096
#define INNER 512
#define HEADS 8
#define DHEAD 64
#define QKV_N (3 * INNER)          // 1536
#define FF_N  (4 * INNER)          // 2048
#define LN_EPS 1e-6f

// exp folding: P = exp((S - m) * 0.125) = ex2((S - m) * CL)
#define CL 0.18033688011112042f    // 0.125 * log2(e)

// ---------------------------------------------------------------------------
// Scratch
// ---------------------------------------------------------------------------
__device__ float g_pp[4][ROWS * INNER];   // proj split-K partials
__device__ float g_fp[4][ROWS * INNER];   // ff   split-K partials
__device__ float g_res1[ROWS * INNER];

__device__ __half g_ah [ROWS * FF_N];    // activations (x / attn / res1)
__device__ __half g_ah2[ROWS * FF_N];    // qkv / mid
__device__ __half g_bh [FF_N * INNER];   // w_ff1
__device__ __half g_bh2[FF_N * INNER];   // w_ff2
__device__ __half g_wq [INNER * QKV_N];  // w_qkv
__device__ __half g_wo [INNER * INNER];  // w_out

// ---------------------------------------------------------------------------
// PTX helpers
// ---------------------------------------------------------------------------
__device__ __forceinline__ void ldsm_x4(uint32_t& r0, uint32_t& r1,
                                        uint32_t& r2, uint32_t& r3, uint32_t addr)
{
    asm volatile("ldmatrix.sync.aligned.m8n8.x4.shared.b16 {%0,%1,%2,%3}, [%4];"
                 : "=r"(r0), "=r"(r1), "=r"(r2), "=r"(r3) : "r"(addr));
}
__device__ __forceinline__ void ldsm_x2t(uint32_t& r0, uint32_t& r1, uint32_t addr)
{
    asm volatile("ldmatrix.sync.aligned.m8n8.x2.trans.shared.b16 {%0,%1}, [%2];"
                 : "=r"(r0), "=r"(r1) : "r"(addr));
}
__device__ __forceinline__ void mma_f16(float* c, const uint32_t* a, const uint32_t* b)
{
    asm volatile(
        "mma.sync.aligned.m16n8k16.row.col.f32.f16.f16.f32 "
        "{%0,%1,%2,%3}, {%4,%5,%6,%7}, {%8,%9}, {%0,%1,%2,%3};"
        : "+f"(c[0]), "+f"(c[1]), "+f"(c[2]), "+f"(c[3])
        : "r"(a[0]), "r"(a[1]), "r"(a[2]), "r"(a[3]), "r"(b[0]), "r"(b[1]));
}
__device__ __forceinline__ void mma_f16acc(uint32_t& c0, uint32_t& c1,
                                           const uint32_t* a, const uint32_t* b)
{
    asm volatile(
        "mma.sync.aligned.m16n8k16.row.col.f16.f16.f16.f16 "
        "{%0,%1}, {%2,%3,%4,%5}, {%6,%7}, {%0,%1};"
        : "+r"(c0), "+r"(c1)
        : "r"(a[0]), "r"(a[1]), "r"(a[2]), "r"(a[3]), "r"(b[0]), "r"(b[1]));
}
__device__ __forceinline__ uint32_t packh2(float a, float b)
{
    __half2 t = __floats2half2_rn(a, b);
    return *reinterpret_cast<uint32_t*>(&t);
}
__device__ __forceinline__ void cp_async16(uint32_t dst, const void* src)
{
    asm volatile("cp.async.cg.shared.global [%0], [%1], 16;"
                 :: "r"(dst), "l"(src));
}
__device__ __forceinline__ float ex2(float x)
{
    float y;
    asm("ex2.approx.f32 %0, %1;" : "=f"(y) : "f"(x));
    return y;
}
__device__ __forceinline__ __half2 h2ex2(__half2 x)
{
    uint32_t xi = *reinterpret_cast<uint32_t*>(&x);
    uint32_t yi;
    asm("ex2.approx.f16x2 %0, %1;" : "=r"(yi) : "r"(xi));
    return *reinterpret_cast<__half2*>(&yi);
}

// ---------------------------------------------------------------------------
// fp32 -> fp16 conversions (fused multi-array)
// ---------------------------------------------------------------------------
__device__ __forceinline__ uint2 h4_of(float4 v)
{
    union { __half2 h[2]; uint2 u; } H;
    H.h[0] = __floats2half2_rn(v.x, v.y);
    H.h[1] = __floats2half2_rn(v.z, v.w);
    return H.u;
}

__global__ __launch_bounds__(256) void cvt_h3_kernel(
    const float4* __restrict__ x0, uint2* __restrict__ h0, int n0,
    const float4* __restrict__ x1, uint2* __restrict__ h1, int n1,
    const float4* __restrict__ x2, uint2* __restrict__ h2, int n2)
{
    int i = blockIdx.x * blockDim.x + threadIdx.x;
    if (i < n0)                { h0[i]           = h4_of(x0[i]); }
    else if (i < n0 + n1)      { h1[i - n0]      = h4_of(x1[i - n0]); }
    else if (i < n0 + n1 + n2) { h2[i - n0 - n1] = h4_of(x2[i - n0 - n1]); }
}

__global__ __launch_bounds__(256) void cvt_h2_kernel(
    const float4* __restrict__ x0, uint2* __restrict__ h0, int n0,
    const float4* __restrict__ x1, uint2* __restrict__ h1, int n1)
{
    int i = blockIdx.x * blockDim.x + threadIdx.x;
    if (i < n0)           { h0[i]      = h4_of(x0[i]); }
    else if (i < n0 + n1) { h1[i - n0] = h4_of(x1[i - n0]); }
}

// ---------------------------------------------------------------------------
// Tensor-core fp16 GEMM (fp32 accum), 128x128xK, 256 threads, 3-stage pipe.
// gridDim.z in {1,2,4} -> split-K: part z writes Cz; bias only on z=0.
// ---------------------------------------------------------------------------
__global__ __launch_bounds__(256) void hgemm_kernel(
    const __half* __restrict__ A, const __half* __restrict__ B,
    const float* __restrict__ bias,
    float* __restrict__ C0, float* __restrict__ C1,
    float* __restrict__ C2, float* __restrict__ C3,
    __half* __restrict__ Ch,
    int M, int N, int Klen, int Ks)
{
    extern __shared__ uint4 smem[];
    uint4* sA = smem;            // [3][512]
    uint4* sB = smem + 3 * 512;  // [3][512]

    const int tid  = threadIdx.x;
    const int lane = tid & 31;
    const int warp = tid >> 5;
    const int wm   = warp >> 2;
    const int wn   = warp & 3;
    const int bm   = blockIdx.y * 128;
    const int bn   = blockIdx.x * 128;
    const int zz   = blockIdx.z;
    const int koff = zz * Klen;

    float* Cout = (zz == 0) ? C0 : (zz == 1) ? C1 : (zz == 2) ? C2 : C3;
    const bool doBias = (bias != nullptr) && (zz == 0);

    const int arow = tid >> 2;
    const int ach  = tid & 3;
    const int brow = tid >> 4;
    const int bch  = tid & 15;

    const int aSwS = ach ^ ((arow >> 1) & 3);
    const int bSwS = bch ^ (brow & 7);

    const uint32_t aBase = (uint32_t)__cvta_generic_to_shared(sA);
    const uint32_t bBase = (uint32_t)__cvta_generic_to_shared(sB);
    const int ar   = wm * 64 + (lane & 15);
    const int aSw  = (ar >> 1) & 3;
    const int aHi  = lane >> 4;
    const int br   = lane & 15;
    const int bSw  = br & 7;

    const int sa0 = arow * 4 + aSwS;
    const int sa1 = (arow + 64) * 4 + aSwS;
    const int sb0 = brow * 16 + bSwS;
    const int sb1 = (brow + 16) * 16 + bSwS;

    float acc[4][4][4];
#pragma unroll
    for (int i = 0; i < 4; i++)
#pragma unroll
        for (int j = 0; j < 4; j++)
#pragma unroll
            for (int r = 0; r < 4; r++) acc[i][j][r] = 0.f;

    auto fill = [&](int kk, int st) {
        uint32_t a0 = aBase + (uint32_t)(st * 8192);
        uint32_t b0 = bBase + (uint32_t)(st * 8192);
        cp_async16(a0 + sa0 * 16, A + (size_t)(bm + arow)      * Ks + koff + kk + ach * 8);
        cp_async16(a0 + sa1 * 16, A + (size_t)(bm + arow + 64) * Ks + koff + kk + ach * 8);
        cp_async16(b0 + sb0 * 16, B + (size_t)(koff + kk + brow)      * N + bn + bch * 8);
        cp_async16(b0 + sb1 * 16, B + (size_t)(koff + kk + brow + 16) * N + bn + bch * 8);
        asm volatile("cp.async.commit_group;");
    };

    const int nIter = Klen / 32;
    fill(0, 0);
    if (nIter > 1) fill(32, 1);

    for (int it = 0; it < nIter; it++) {
        const int st = it % 3;
        if (it + 1 < nIter) {
            asm volatile("cp.async.wait_group 1;");
        } else {
            asm volatile("cp.async.wait_group 0;");
        }
        __syncthreads();
        if (it + 2 < nIter) fill((it + 2) * 32, (it + 2) % 3);

#pragma unroll
        for (int s = 0; s < 2; s++) {
            uint32_t Af[4][4];
            uint32_t Bf[4][2];
#pragma unroll
            for (int i = 0; i < 4; i++) {
                uint32_t addr = aBase + (uint32_t)(st * 8192 +
                    (ar + i * 16) * 64 + (((2 * s + aHi) ^ aSw) * 16));
                ldsm_x4(Af[i][0], Af[i][1], Af[i][2], Af[i][3], addr);
            }
#pragma unroll
            for (int j = 0; j < 4; j++) {
                uint32_t addr = bBase + (uint32_t)(st * 8192 +
                    (s * 16 + br) * 256 + ((((wn << 2) + j) ^ bSw) * 16));
                ldsm_x2t(Bf[j][0], Bf[j][1], addr);
            }
#pragma unroll
            for (int i = 0; i < 4; i++)
#pragma unroll
                for (int j = 0; j < 4; j++)
                    mma_f16(acc[i][j], Af[i], Bf[j]);
        }
    }

    const int grp = lane >> 2;
    const int qc  = (lane & 3) * 2;
#pragma unroll
    for (int i = 0; i < 4; i++) {
#pragma unroll
        for (int j = 0; j < 4; j++) {
            int row = bm + wm * 64 + i * 16 + grp;
            int col = bn + wn * 32 + j * 8 + qc;
            float b0 = 0.f, b1 = 0.f;
            if (doBias) { b0 = bias[col]; b1 = bias[col + 1]; }
            float v00 = acc[i][j][0] + b0, v01 = acc[i][j][1] + b1;
            float v10 = acc[i][j][2] + b0, v11 = acc[i][j][3] + b1;
            if (Cout) {
                *(float2*)(Cout + (size_t)row * N + col)       = make_float2(v00, v01);
                *(float2*)(Cout + (size_t)(row + 8) * N + col) = make_float2(v10, v11);
            }
            if (Ch) {
                *(uint32_t*)(Ch + (size_t)row * N + col)       = packh2(v00, v01);
                *(uint32_t*)(Ch + (size_t)(row + 8) * N + col) = packh2(v10, v11);
            }
        }
    }
}

// ---------------------------------------------------------------------------
// Flash attention (round-13 config): fp16 accumulators, KB=64, 3-stage
// cp.async pipeline, 128 q-rows/CTA (32/warp), h2 softmax.
// ---------------------------------------------------------------------------
__global__ __launch_bounds__(128) void attn_mma_kernel(
    const __half* __restrict__ qh, __half* __restrict__ outH)
{
    __shared__ uint4 sK[3][512];
    __shared__ uint4 sV[3][512];

    const int tid  = threadIdx.x;
    const int lane = tid & 31;
    const int warp = tid >> 5;
    const int g    = lane >> 2;
    const int t    = lane & 3;
    const int b    = blockIdx.y >> 3;
    const int h    = blockIdx.y & 7;
    const int q0   = blockIdx.x * 128;

    uint32_t Qh[2][4][4];
#pragma unroll
    for (int u = 0; u < 2; u++) {
#pragma unroll
        for (int kt = 0; kt < 4; kt++) {
#pragma unroll
            for (int p = 0; p < 4; p++) {
                size_t row = (size_t)(b * SEQ + q0 + warp * 32 + u * 16 + g + (p & 1) * 8);
                int col = h * DHEAD + kt * 16 + (p >> 1) * 8 + 2 * t;
                Qh[u][kt][p] = *(const uint32_t*)(qh + row * QKV_N + col);
            }
        }
    }

    const uint32_t kBase = (uint32_t)__cvta_generic_to_shared(&sK[0][0]);
    const uint32_t vBase = (uint32_t)__cvta_generic_to_shared(&sV[0][0]);

    uint32_t O[2][8][2];
#pragma unroll
    for (int u = 0; u < 2; u++)
#pragma unroll
        for (int j = 0; j < 8; j++) { O[u][j][0] = 0u; O[u][j][1] = 0u; }
    float m[2][2], l[2][2];
#pragma unroll
    for (int u = 0; u < 2; u++) { m[u][0] = m[u][1] = -1e30f; l[u][0] = l[u][1] = 0.f; }

    const __half2 CL2 = __float2half2_rn(CL);

    const int kRowOff = (lane & 7) + ((lane >> 4) << 3);
    const int kHalf   = (lane >> 3) & 1;
    const int vRowOff = lane & 15;

    const int fr  = tid >> 1;
    const int fhf = tid & 1;
    const int fsw = fr & 7;

    auto fill = [&](int kb, int stage) {
        size_t rowoff = (size_t)(b * SEQ + kb * 64 + fr) * QKV_N + h * DHEAD + fhf * 32;
        const __half* kr = qh + rowoff + INNER;
        const __half* vr = qh + rowoff + 2 * INNER;
#pragma unroll
        for (int c = 0; c < 4; c++) {
            int cc = (fhf * 4 + c) ^ fsw;
            uint32_t off = (uint32_t)((stage * 512 + fr * 8 + cc) * 16);
            cp_async16(kBase + off, kr + c * 8);
            cp_async16(vBase + off, vr + c * 8);
        }
        asm volatile("cp.async.commit_group;");
    };

    constexpr int NB = SEQ / 64;
    fill(0, 0);
    fill(1, 1);

    for (int kb = 0; kb < NB; kb++) {
        const int stage = kb % 3;
        if (kb + 1 < NB) {
            asm volatile("cp.async.wait_group 1;");
        } else {
            asm volatile("cp.async.wait_group 0;");
        }
        __syncthreads();
        if (kb + 2 < NB) fill(kb + 2, (kb + 2) % 3);

        uint32_t S[2][8][2];
#pragma unroll
        for (int u = 0; u < 2; u++)
#pragma unroll
            for (int j = 0; j < 8; j++) { S[u][j][0] = 0u; S[u][j][1] = 0u; }

#pragma unroll
        for (int kt = 0; kt < 4; kt++) {
            uint32_t Bh[8][2];
#pragma unroll
            for (int jp = 0; jp < 4; jp++) {
                int row = jp * 16 + kRowOff;
                uint32_t off = (uint32_t)((stage * 512 + row * 8 +
                                           ((2 * kt + kHalf) ^ (row & 7))) * 16);
                ldsm_x4(Bh[2 * jp][0], Bh[2 * jp][1], Bh[2 * jp + 1][0], Bh[2 * jp + 1][1],
                        kBase + off);
            }
#pragma unroll
            for (int j = 0; j < 8; j++) {
                mma_f16acc(S[0][j][0], S[0][j][1], Qh[0][kt], Bh[j]);
                mma_f16acc(S[1][j][0], S[1][j][1], Qh[1][kt], Bh[j]);
            }
        }

#pragma unroll
        for (int u = 0; u < 2; u++) {
            __half2 mh0 = __float2half2_rn(-60000.f);
            __half2 mh1 = mh0;
#pragma unroll
            for (int j = 0; j < 8; j++) {
                mh0 = __hmax2(mh0, *reinterpret_cast<__half2*>(&S[u][j][0]));
                mh1 = __hmax2(mh1, *reinterpret_cast<__half2*>(&S[u][j][1]));
            }
            float mx0 = fmaxf(__low2float(mh0), __high2float(mh0));
            float mx1 = fmaxf(__low2float(mh1), __high2float(mh1));
            mx0 = fmaxf(mx0, __shfl_xor_sync(0xffffffffu, mx0, 1));
            mx0 = fmaxf(mx0, __shfl_xor_sync(0xffffffffu, mx0, 2));
            mx1 = fmaxf(mx1, __shfl_xor_sync(0xffffffffu, mx1, 1));
            mx1 = fmaxf(mx1, __shfl_xor_sync(0xffffffffu, mx1, 2));
            float mn0 = fmaxf(m[u][0], mx0);
            float mn1 = fmaxf(m[u][1], mx1);
            float a0 = ex2((m[u][0] - mn0) * CL);
            float a1 = ex2((m[u][1] - mn1) * CL);
            m[u][0] = mn0; m[u][1] = mn1;

            __half2 nm0 = __float2half2_rn(mn0);
            __half2 nm1 = __float2half2_rn(mn1);
            __half2 sum0 = __float2half2_rn(0.f);
            __half2 sum1 = sum0;
#pragma unroll
            for (int j = 0; j < 8; j++) {
                __half2 s0 = *reinterpret_cast<__half2*>(&S[u][j][0]);
                __half2 s1 = *reinterpret_cast<__half2*>(&S[u][j][1]);
                __half2 e0 = h2ex2(__hmul2(__hsub2(s0, nm0), CL2));
                __half2 e1 = h2ex2(__hmul2(__hsub2(s1, nm1), CL2));
                *reinterpret_cast<__half2*>(&S[u][j][0]) = e0;
                *reinterpret_cast<__half2*>(&S[u][j][1]) = e1;
                sum0 = __hadd2(sum0, e0);
                sum1 = __hadd2(sum1, e1);
            }
            float s0 = __low2float(sum0) + __high2float(sum0);
            float s1 = __low2float(sum1) + __high2float(sum1);
            s0 += __shfl_xor_sync(0xffffffffu, s0, 1);
            s0 += __shfl_xor_sync(0xffffffffu, s0, 2);
            s1 += __shfl_xor_sync(0xffffffffu, s1, 1);
            s1 += __shfl_xor_sync(0xffffffffu, s1, 2);
            l[u][0] = l[u][0] * a0 + s0;
            l[u][1] = l[u][1] * a1 + s1;

            __half2 a0h = __float2half2_rn(a0);
            __half2 a1h = __float2half2_rn(a1);
#pragma unroll
            for (int j = 0; j < 8; j++) {
                __half2 o0 = *reinterpret_cast<__half2*>(&O[u][j][0]);
                __half2 o1 = *reinterpret_cast<__half2*>(&O[u][j][1]);
                o0 = __hmul2(o0, a0h);
                o1 = __hmul2(o1, a1h);
                *reinterpret_cast<__half2*>(&O[u][j][0]) = o0;
                *reinterpret_cast<__half2*>(&O[u][j][1]) = o1;
            }
        }

#pragma unroll
        for (int kt = 0; kt < 4; kt++) {
            uint32_t Vb[8][2];
#pragma unroll
            for (int j = 0; j < 8; j++) {
                int row = kt * 16 + vRowOff;
                uint32_t off = (uint32_t)((stage * 512 + row * 8 + (j ^ (row & 7))) * 16);
                ldsm_x2t(Vb[j][0], Vb[j][1], vBase + off);
            }
            uint32_t Pa0[4] = { S[0][2 * kt][0], S[0][2 * kt][1],
                                S[0][2 * kt + 1][0], S[0][2 * kt + 1][1] };
            uint32_t Pa1[4] = { S[1][2 * kt][0], S[1][2 * kt][1],
                                S[1][2 * kt + 1][0], S[1][2 * kt + 1][1] };
#pragma unroll
            for (int j = 0; j < 8; j++) {
                mma_f16acc(O[0][j][0], O[0][j][1], Pa0, Vb[j]);
                mma_f16acc(O[1][j][0], O[1][j][1], Pa1, Vb[j]);
            }
        }
    }

#pragma unroll
    for (int u = 0; u < 2; u++) {
        __half2 il0 = __float2half2_rn(1.f / l[u][0]);
        __half2 il1 = __float2half2_rn(1.f / l[u][1]);
        int row0 = b * SEQ + q0 + warp * 32 + u * 16 + g;
#pragma unroll
        for (int j = 0; j < 8; j++) {
            int col = h * DHEAD + j * 8 + 2 * t;
            __half2 o0 = __hmul2(*reinterpret_cast<__half2*>(&O[u][j][0]), il0);
            __half2 o1 = __hmul2(*reinterpret_cast<__half2*>(&O[u][j][1]), il1);
            *(__half2*)(outH + (size_t)row0 * INNER + col)       = o0;
            *(__half2*)(outH + (size_t)(row0 + 8) * INNER + col) = o1;
        }
    }
}

// ---------------------------------------------------------------------------
// Fused residual + LayerNorm: out = LN(A + B0 + B1 + B2 + B3), B1..B3 optional.
// ---------------------------------------------------------------------------
__global__ __launch_bounds__(128) void ln_res_kernel(
    const float* __restrict__ A, const float* __restrict__ B0,
    const float* __restrict__ B1, const float* __restrict__ B2,
    const float* __restrict__ B3,
    const float* __restrict__ g, const float* __restrict__ be,
    float* __restrict__ out, __half* __restrict__ outH)
{
    const int row = blockIdx.x;
    const int tid = threadIdx.x;
    const size_t off = (size_t)row * INNER + tid * 4;

    float4 va = *(const float4*)(A + off);
    float4 vb = *(const float4*)(B0 + off);
    float x0 = va.x + vb.x, x1 = va.y + vb.y, x2 = va.z + vb.z, x3 = va.w + vb.w;
    if (B1) {
        float4 vc = *(const float4*)(B1 + off);
        x0 += vc.x; x1 += vc.y; x2 += vc.z; x3 += vc.w;
    }
    if (B2) {
        float4 vc = *(const float4*)(B2 + off);
        x0 += vc.x; x1 += vc.y; x2 += vc.z; x3 += vc.w;
    }
    if (B3) {
        float4 vc = *(const float4*)(B3 + off);
        x0 += vc.x; x1 += vc.y; x2 += vc.z; x3 += vc.w;
    }

    float s  = x0 + x1 + x2 + x3;
    float s2 = x0 * x0 + x1 * x1 + x2 * x2 + x3 * x3;
#pragma unroll
    for (int o2 = 16; o2 >= 1; o2 >>= 1) {
        s  += __shfl_xor_sync(0xffffffffu, s,  o2);
        s2 += __shfl_xor_sync(0xffffffffu, s2, o2);
    }
    __shared__ float sh[8];
    int w = tid >> 5;
    if ((tid & 31) == 0) { sh[w] = s; sh[4 + w] = s2; }
    __syncthreads();
    s  = sh[0] + sh[1] + sh[2] + sh[3];
    s2 = sh[4] + sh[5] + sh[6] + sh[7];

    const float inv_n = 1.f / (float)INNER;
    float mu   = s * inv_n;
    float var  = s2 * inv_n - mu * mu;
    float rstd = rsqrtf(var + LN_EPS);

    float4 vg  = *(const float4*)(g  + tid * 4);
    float4 vbe = *(const float4*)(be + tid * 4);
    float4 vo;
    vo.x = (x0 - mu) * rstd * vg.x + vbe.x;
    vo.y = (x1 - mu) * rstd * vg.y + vbe.y;
    vo.z = (x2 - mu) * rstd * vg.z + vbe.z;
    vo.w = (x3 - mu) * rstd * vg.w + vbe.w;
    *(float4*)(out + off) = vo;

    if (outH) {
        *(uint2*)(outH + off) = make_uint2(packh2(vo.x, vo.y), packh2(vo.z, vo.w));
    }
}

// ---------------------------------------------------------------------------
// Launch
// ---------------------------------------------------------------------------
#define GEMM_SMEM 49152

extern "C" void kernel_launch(void* const* d_in, const int* in_sizes, int n_in,
                              void* d_out, int out_size)
{
    const float* x     = (const float*)d_in[0];
    const float* w_qkv = (const float*)d_in[1];
    const float* w_out = (const float*)d_in[2];
    const float* b_out = (const float*)d_in[3];
    const float* w_ff1 = (const float*)d_in[4];
    const float* w_ff2 = (const float*)d_in[5];
    const float* g1    = (const float*)d_in[6];
    const float* be1   = (const float*)d_in[7];
    const float* g2    = (const float*)d_in[8];
    const float* be2   = (const float*)d_in[9];
    float* out = (float*)d_out;

    float *res1, *pp, *fp;
    __half *ah, *ah2, *bh, *bh2, *wq, *wo;
    cudaGetSymbolAddress((void**)&res1, g_res1);
    cudaGetSymbolAddress((void**)&pp,   g_pp);
    cudaGetSymbolAddress((void**)&fp,   g_fp);
    cudaGetSymbolAddress((void**)&ah,   g_ah);
    cudaGetSymbolAddress((void**)&ah2,  g_ah2);
    cudaGetSymbolAddress((void**)&bh,   g_bh);
    cudaGetSymbolAddress((void**)&bh2,  g_bh2);
    cudaGetSymbolAddress((void**)&wq,   g_wq);
    cudaGetSymbolAddress((void**)&wo,   g_wo);

    const size_t PLANE = (size_t)ROWS * INNER;
    float* pp0 = pp;             float* pp1 = pp + PLANE;
    float* pp2 = pp + 2 * PLANE; float* pp3 = pp + 3 * PLANE;
    float* fp0 = fp;             float* fp1 = fp + PLANE;
    float* fp2 = fp + 2 * PLANE; float* fp3 = fp + 3 * PLANE;

    cudaFuncSetAttribute(hgemm_kernel,
                         cudaFuncAttributeMaxDynamicSharedMemorySize, GEMM_SMEM);

    // 0a) fp16 conversions: x -> ah, w_qkv -> wq, w_out -> wo
    {
        int n0 = ROWS * INNER / 4, n1 = INNER * QKV_N / 4, n2 = INNER * INNER / 4;
        int tot = n0 + n1 + n2;
        cvt_h3_kernel<<<(tot + 255) / 256, 256>>>(
            (const float4*)x, (uint2*)ah, n0,
            (const float4*)w_qkv, (uint2*)wq, n1,
            (const float4*)w_out, (uint2*)wo, n2);
    }
    // 0b) fp16 conversions: w_ff1 -> bh, w_ff2 -> bh2
    {
        int n0 = INNER * FF_N / 4, n1 = FF_N * INNER / 4;
        cvt_h2_kernel<<<(n0 + n1 + 255) / 256, 256>>>(
            (const float4*)w_ff1, (uint2*)bh, n0,
            (const float4*)w_ff2, (uint2*)bh2, n1);
    }

    // 1) qkv = x @ w_qkv  (fp16 -> fp16 out)
    hgemm_kernel<<<dim3(QKV_N / 128, ROWS / 128, 1), 256, GEMM_SMEM>>>(
        ah, wq, nullptr, nullptr, nullptr, nullptr, nullptr, ah2,
        ROWS, QKV_N, INNER, INNER);

    // 2) attention -> fp16 attn out (R13 config)
    attn_mma_kernel<<<dim3(SEQ / 128, BATCH * HEADS), 128>>>(ah2, ah);

    // 3) proj = attn @ w_out + b_out  (split-K=4 -> pp0..pp3, fp32)
    hgemm_kernel<<<dim3(INNER / 128, ROWS / 128, 4), 256, GEMM_SMEM>>>(
        ah, wo, b_out, pp0, pp1, pp2, pp3, nullptr,
        ROWS, INNER, INNER / 4, INNER);

    // 4) res1 = LN(x + pp0..3), emit fp16
    ln_res_kernel<<<ROWS, 128>>>(x, pp0, pp1, pp2, pp3, g1, be1, res1, ah);

    // 5) mid = res1 @ w_ff1 -> fp16
    hgemm_kernel<<<dim3(FF_N / 128, ROWS / 128, 1), 256, GEMM_SMEM>>>(
        ah, bh, nullptr, nullptr, nullptr, nullptr, nullptr, ah2,
        ROWS, FF_N, INNER, INNER);

    // 6) ff = mid @ w_ff2 (split-K=4 -> fp0..fp3, fp32)
    hgemm_kernel<<<dim3(INNER / 128, ROWS / 128, 4), 256, GEMM_SMEM>>>(
        ah2, bh2, nullptr, fp0, fp1, fp2, fp3, nullptr,
        ROWS, INNER, FF_N / 4, FF_N);

    // 7) out = LN(res1 + fp0..3)
    ln_res_kernel<<<ROWS, 128>>>(res1, fp0, fp1, fp2, fp3, g2, be2, out, nullptr);
}

// round 17
// speedup vs baseline: 1.0915x; 1.0826x over previous
#include <cuda_runtime.h>
#include <cuda_fp16.h>
#include <math.h>
#include <stdint.h>

// Problem constants
#define BATCH 2
#define SEQ   2048
#define ROWS  (BATCH * SEQ)        // 4096
#define INNER 512
#define HEADS 8
#define DHEAD 64
#define QKV_N (3 * INNER)          // 1536
#define FF_N  (4 * INNER)          // 2048
#define LN_EPS 1e-6f

// exp folding: P = exp((S - m) * 0.125) = ex2((S - m) * CL)
#define CL 0.18033688011112042f    // 0.125 * log2(e)

// ---------------------------------------------------------------------------
// Scratch
// ---------------------------------------------------------------------------
__device__ float g_proj [ROWS * INNER];
__device__ float g_projB[ROWS * INNER];
__device__ float g_res1 [ROWS * INNER];
__device__ float g_ff   [ROWS * INNER];
__device__ float g_ffB  [ROWS * INNER];

__device__ __half g_ah [ROWS * FF_N];    // activations (x / attn / res1)
__device__ __half g_ah2[ROWS * FF_N];    // qkv / mid
__device__ __half g_bh [FF_N * INNER];   // w_ff1
__device__ __half g_bh2[FF_N * INNER];   // w_ff2
__device__ __half g_wq [INNER * QKV_N];  // w_qkv
__device__ __half g_wo [INNER * INNER];  // w_out

// ---------------------------------------------------------------------------
// PTX helpers
// ---------------------------------------------------------------------------
__device__ __forceinline__ void ldsm_x4(uint32_t& r0, uint32_t& r1,
                                        uint32_t& r2, uint32_t& r3, uint32_t addr)
{
    asm volatile("ldmatrix.sync.aligned.m8n8.x4.shared.b16 {%0,%1,%2,%3}, [%4];"
                 : "=r"(r0), "=r"(r1), "=r"(r2), "=r"(r3) : "r"(addr));
}
__device__ __forceinline__ void ldsm_x2t(uint32_t& r0, uint32_t& r1, uint32_t addr)
{
    asm volatile("ldmatrix.sync.aligned.m8n8.x2.trans.shared.b16 {%0,%1}, [%2];"
                 : "=r"(r0), "=r"(r1) : "r"(addr));
}
__device__ __forceinline__ void mma_f16(float* c, const uint32_t* a, const uint32_t* b)
{
    asm volatile(
        "mma.sync.aligned.m16n8k16.row.col.f32.f16.f16.f32 "
        "{%0,%1,%2,%3}, {%4,%5,%6,%7}, {%8,%9}, {%0,%1,%2,%3};"
        : "+f"(c[0]), "+f"(c[1]), "+f"(c[2]), "+f"(c[3])
        : "r"(a[0]), "r"(a[1]), "r"(a[2]), "r"(a[3]), "r"(b[0]), "r"(b[1]));
}
__device__ __forceinline__ void mma_f16acc(uint32_t& c0, uint32_t& c1,
                                           const uint32_t* a, const uint32_t* b)
{
    asm volatile(
        "mma.sync.aligned.m16n8k16.row.col.f16.f16.f16.f16 "
        "{%0,%1}, {%2,%3,%4,%5}, {%6,%7}, {%0,%1};"
        : "+r"(c0), "+r"(c1)
        : "r"(a[0]), "r"(a[1]), "r"(a[2]), "r"(a[3]), "r"(b[0]), "r"(b[1]));
}
__device__ __forceinline__ uint32_t packh2(float a, float b)
{
    __half2 t = __floats2half2_rn(a, b);
    return *reinterpret_cast<uint32_t*>(&t);
}
__device__ __forceinline__ void cp_async16(uint32_t dst, const void* src)
{
    asm volatile("cp.async.cg.shared.global [%0], [%1], 16;"
                 :: "r"(dst), "l"(src));
}
__device__ __forceinline__ float ex2(float x)
{
    float y;
    asm("ex2.approx.f32 %0, %1;" : "=f"(y) : "f"(x));
    return y;
}
__device__ __forceinline__ __half2 h2ex2(__half2 x)
{
    uint32_t xi = *reinterpret_cast<uint32_t*>(&x);
    uint32_t yi;
    asm("ex2.approx.f16x2 %0, %1;" : "=r"(yi) : "r"(xi));
    return *reinterpret_cast<__half2*>(&yi);
}

// ---------------------------------------------------------------------------
// fp32 -> fp16 conversion, all 5 arrays in one launch
// ---------------------------------------------------------------------------
__device__ __forceinline__ uint2 h4_of(float4 v)
{
    union { __half2 h[2]; uint2 u; } H;
    H.h[0] = __floats2half2_rn(v.x, v.y);
    H.h[1] = __floats2half2_rn(v.z, v.w);
    return H.u;
}

__global__ __launch_bounds__(256) void cvt_h5_kernel(
    const float4* __restrict__ x0, uint2* __restrict__ h0, int n0,
    const float4* __restrict__ x1, uint2* __restrict__ h1, int n1,
    const float4* __restrict__ x2, uint2* __restrict__ h2, int n2,
    const float4* __restrict__ x3, uint2* __restrict__ h3, int n3,
    const float4* __restrict__ x4, uint2* __restrict__ h4, int n4)
{
    int i = blockIdx.x * blockDim.x + threadIdx.x;
    if (i < n0) { h0[i] = h4_of(x0[i]); return; }
    i -= n0;
    if (i < n1) { h1[i] = h4_of(x1[i]); return; }
    i -= n1;
    if (i < n2) { h2[i] = h4_of(x2[i]); return; }
    i -= n2;
    if (i < n3) { h3[i] = h4_of(x3[i]); return; }
    i -= n3;
    if (i < n4) { h4[i] = h4_of(x4[i]); }
}

// ---------------------------------------------------------------------------
// Tensor-core fp16 GEMM (fp32 accum), 128x128xK, 256 threads, 3-stage pipe.
// gridDim.z == 2 -> split-K: z=0 writes C (+bias), z=1 writes C2.
// ---------------------------------------------------------------------------
__global__ __launch_bounds__(256) void hgemm_kernel(
    const __half* __restrict__ A, const __half* __restrict__ B,
    const float* __restrict__ bias, float* __restrict__ C, float* __restrict__ C2,
    __half* __restrict__ Ch,
    int M, int N, int Klen, int Ks)
{
    extern __shared__ uint4 smem[];
    uint4* sA = smem;            // [3][512]
    uint4* sB = smem + 3 * 512;  // [3][512]

    const int tid  = threadIdx.x;
    const int lane = tid & 31;
    const int warp = tid >> 5;
    const int wm   = warp >> 2;
    const int wn   = warp & 3;
    const int bm   = blockIdx.y * 128;
    const int bn   = blockIdx.x * 128;
    const int zz   = blockIdx.z;
    const int koff = zz * Klen;

    float* Cout = zz ? C2 : C;
    const bool doBias = (bias != nullptr) && (zz == 0);

    const int arow = tid >> 2;
    const int ach  = tid & 3;
    const int brow = tid >> 4;
    const int bch  = tid & 15;

    const int aSwS = ach ^ ((arow >> 1) & 3);
    const int bSwS = bch ^ (brow & 7);

    const uint32_t aBase = (uint32_t)__cvta_generic_to_shared(sA);
    const uint32_t bBase = (uint32_t)__cvta_generic_to_shared(sB);
    const int ar   = wm * 64 + (lane & 15);
    const int aSw  = (ar >> 1) & 3;
    const int aHi  = lane >> 4;
    const int br   = lane & 15;
    const int bSw  = br & 7;

    const int sa0 = arow * 4 + aSwS;
    const int sa1 = (arow + 64) * 4 + aSwS;
    const int sb0 = brow * 16 + bSwS;
    const int sb1 = (brow + 16) * 16 + bSwS;

    float acc[4][4][4];
#pragma unroll
    for (int i = 0; i < 4; i++)
#pragma unroll
        for (int j = 0; j < 4; j++)
#pragma unroll
            for (int r = 0; r < 4; r++) acc[i][j][r] = 0.f;

    auto fill = [&](int kk, int st) {
        uint32_t a0 = aBase + (uint32_t)(st * 8192);
        uint32_t b0 = bBase + (uint32_t)(st * 8192);
        cp_async16(a0 + sa0 * 16, A + (size_t)(bm + arow)      * Ks + koff + kk + ach * 8);
        cp_async16(a0 + sa1 * 16, A + (size_t)(bm + arow + 64) * Ks + koff + kk + ach * 8);
        cp_async16(b0 + sb0 * 16, B + (size_t)(koff + kk + brow)      * N + bn + bch * 8);
        cp_async16(b0 + sb1 * 16, B + (size_t)(koff + kk + brow + 16) * N + bn + bch * 8);
        asm volatile("cp.async.commit_group;");
    };

    const int nIter = Klen / 32;
    fill(0, 0);
    fill(32, 1);

    for (int it = 0; it < nIter; it++) {
        const int st = it % 3;
        if (it + 1 < nIter) {
            asm volatile("cp.async.wait_group 1;");
        } else {
            asm volatile("cp.async.wait_group 0;");
        }
        __syncthreads();
        if (it + 2 < nIter) fill((it + 2) * 32, (it + 2) % 3);

#pragma unroll
        for (int s = 0; s < 2; s++) {
            uint32_t Af[4][4];
            uint32_t Bf[4][2];
#pragma unroll
            for (int i = 0; i < 4; i++) {
                uint32_t addr = aBase + (uint32_t)(st * 8192 +
                    (ar + i * 16) * 64 + (((2 * s + aHi) ^ aSw) * 16));
                ldsm_x4(Af[i][0], Af[i][1], Af[i][2], Af[i][3], addr);
            }
#pragma unroll
            for (int j = 0; j < 4; j++) {
                uint32_t addr = bBase + (uint32_t)(st * 8192 +
                    (s * 16 + br) * 256 + ((((wn << 2) + j) ^ bSw) * 16));
                ldsm_x2t(Bf[j][0], Bf[j][1], addr);
            }
#pragma unroll
            for (int i = 0; i < 4; i++)
#pragma unroll
                for (int j = 0; j < 4; j++)
                    mma_f16(acc[i][j], Af[i], Bf[j]);
        }
    }

    const int grp = lane >> 2;
    const int qc  = (lane & 3) * 2;
#pragma unroll
    for (int i = 0; i < 4; i++) {
#pragma unroll
        for (int j = 0; j < 4; j++) {
            int row = bm + wm * 64 + i * 16 + grp;
            int col = bn + wn * 32 + j * 8 + qc;
            float b0 = 0.f, b1 = 0.f;
            if (doBias) { b0 = bias[col]; b1 = bias[col + 1]; }
            float v00 = acc[i][j][0] + b0, v01 = acc[i][j][1] + b1;
            float v10 = acc[i][j][2] + b0, v11 = acc[i][j][3] + b1;
            if (Cout) {
                *(float2*)(Cout + (size_t)row * N + col)       = make_float2(v00, v01);
                *(float2*)(Cout + (size_t)(row + 8) * N + col) = make_float2(v10, v11);
            }
            if (Ch) {
                *(uint32_t*)(Ch + (size_t)row * N + col)       = packh2(v00, v01);
                *(uint32_t*)(Ch + (size_t)(row + 8) * N + col) = packh2(v10, v11);
            }
        }
    }
}

// ---------------------------------------------------------------------------
// Tensor-core fp16 GEMM with fp16 accumulators (2x rate) — for qkv.
// 128x128xK, 256 threads, 3-stage pipe, fp16 output only, no bias/split.
// ---------------------------------------------------------------------------
__global__ __launch_bounds__(256) void hgemm16_kernel(
    const __half* __restrict__ A, const __half* __restrict__ B,
    __half* __restrict__ Ch, int M, int N, int K)
{
    extern __shared__ uint4 smem[];
    uint4* sA = smem;            // [3][512]
    uint4* sB = smem + 3 * 512;  // [3][512]

    const int tid  = threadIdx.x;
    const int lane = tid & 31;
    const int warp = tid >> 5;
    const int wm   = warp >> 2;
    const int wn   = warp & 3;
    const int bm   = blockIdx.y * 128;
    const int bn   = blockIdx.x * 128;

    const int arow = tid >> 2;
    const int ach  = tid & 3;
    const int brow = tid >> 4;
    const int bch  = tid & 15;

    const int aSwS = ach ^ ((arow >> 1) & 3);
    const int bSwS = bch ^ (brow & 7);

    const uint32_t aBase = (uint32_t)__cvta_generic_to_shared(sA);
    const uint32_t bBase = (uint32_t)__cvta_generic_to_shared(sB);
    const int ar   = wm * 64 + (lane & 15);
    const int aSw  = (ar >> 1) & 3;
    const int aHi  = lane >> 4;
    const int br   = lane & 15;
    const int bSw  = br & 7;

    const int sa0 = arow * 4 + aSwS;
    const int sa1 = (arow + 64) * 4 + aSwS;
    const int sb0 = brow * 16 + bSwS;
    const int sb1 = (brow + 16) * 16 + bSwS;

    uint32_t acc[4][4][2];
#pragma unroll
    for (int i = 0; i < 4; i++)
#pragma unroll
        for (int j = 0; j < 4; j++) { acc[i][j][0] = 0u; acc[i][j][1] = 0u; }

    auto fill = [&](int kk, int st) {
        uint32_t a0 = aBase + (uint32_t)(st * 8192);
        uint32_t b0 = bBase + (uint32_t)(st * 8192);
        cp_async16(a0 + sa0 * 16, A + (size_t)(bm + arow)      * K + kk + ach * 8);
        cp_async16(a0 + sa1 * 16, A + (size_t)(bm + arow + 64) * K + kk + ach * 8);
        cp_async16(b0 + sb0 * 16, B + (size_t)(kk + brow)      * N + bn + bch * 8);
        cp_async16(b0 + sb1 * 16, B + (size_t)(kk + brow + 16) * N + bn + bch * 8);
        asm volatile("cp.async.commit_group;");
    };

    const int nIter = K / 32;
    fill(0, 0);
    fill(32, 1);

    for (int it = 0; it < nIter; it++) {
        const int st = it % 3;
        if (it + 1 < nIter) {
            asm volatile("cp.async.wait_group 1;");
        } else {
            asm volatile("cp.async.wait_group 0;");
        }
        __syncthreads();
        if (it + 2 < nIter) fill((it + 2) * 32, (it + 2) % 3);

#pragma unroll
        for (int s = 0; s < 2; s++) {
            uint32_t Af[4][4];
            uint32_t Bf[4][2];
#pragma unroll
            for (int i = 0; i < 4; i++) {
                uint32_t addr = aBase + (uint32_t)(st * 8192 +
                    (ar + i * 16) * 64 + (((2 * s + aHi) ^ aSw) * 16));
                ldsm_x4(Af[i][0], Af[i][1], Af[i][2], Af[i][3], addr);
            }
#pragma unroll
            for (int j = 0; j < 4; j++) {
                uint32_t addr = bBase + (uint32_t)(st * 8192 +
                    (s * 16 + br) * 256 + ((((wn << 2) + j) ^ bSw) * 16));
                ldsm_x2t(Bf[j][0], Bf[j][1], addr);
            }
#pragma unroll
            for (int i = 0; i < 4; i++)
#pragma unroll
                for (int j = 0; j < 4; j++)
                    mma_f16acc(acc[i][j][0], acc[i][j][1], Af[i], Bf[j]);
        }
    }

    const int grp = lane >> 2;
    const int qc  = (lane & 3) * 2;
#pragma unroll
    for (int i = 0; i < 4; i++) {
#pragma unroll
        for (int j = 0; j < 4; j++) {
            int row = bm + wm * 64 + i * 16 + grp;
            int col = bn + wn * 32 + j * 8 + qc;
            *(uint32_t*)(Ch + (size_t)row * N + col)       = acc[i][j][0];
            *(uint32_t*)(Ch + (size_t)(row + 8) * N + col) = acc[i][j][1];
        }
    }
}

// ---------------------------------------------------------------------------
// Flash attention (round-13 config): fp16 accumulators, KB=64, 3-stage
// cp.async pipeline, 128 q-rows/CTA (32/warp), h2 softmax.
// ---------------------------------------------------------------------------
__global__ __launch_bounds__(128) void attn_mma_kernel(
    const __half* __restrict__ qh, __half* __restrict__ outH)
{
    __shared__ uint4 sK[3][512];
    __shared__ uint4 sV[3][512];

    const int tid  = threadIdx.x;
    const int lane = tid & 31;
    const int warp = tid >> 5;
    const int g    = lane >> 2;
    const int t    = lane & 3;
    const int b    = blockIdx.y >> 3;
    const int h    = blockIdx.y & 7;
    const int q0   = blockIdx.x * 128;

    uint32_t Qh[2][4][4];
#pragma unroll
    for (int u = 0; u < 2; u++) {
#pragma unroll
        for (int kt = 0; kt < 4; kt++) {
#pragma unroll
            for (int p = 0; p < 4; p++) {
                size_t row = (size_t)(b * SEQ + q0 + warp * 32 + u * 16 + g + (p & 1) * 8);
                int col = h * DHEAD + kt * 16 + (p >> 1) * 8 + 2 * t;
                Qh[u][kt][p] = *(const uint32_t*)(qh + row * QKV_N + col);
            }
        }
    }

    const uint32_t kBase = (uint32_t)__cvta_generic_to_shared(&sK[0][0]);
    const uint32_t vBase = (uint32_t)__cvta_generic_to_shared(&sV[0][0]);

    uint32_t O[2][8][2];
#pragma unroll
    for (int u = 0; u < 2; u++)
#pragma unroll
        for (int j = 0; j < 8; j++) { O[u][j][0] = 0u; O[u][j][1] = 0u; }
    float m[2][2], l[2][2];
#pragma unroll
    for (int u = 0; u < 2; u++) { m[u][0] = m[u][1] = -1e30f; l[u][0] = l[u][1] = 0.f; }

    const __half2 CL2 = __float2half2_rn(CL);

    const int kRowOff = (lane & 7) + ((lane >> 4) << 3);
    const int kHalf   = (lane >> 3) & 1;
    const int vRowOff = lane & 15;

    const int fr  = tid >> 1;
    const int fhf = tid & 1;
    const int fsw = fr & 7;

    auto fill = [&](int kb, int stage) {
        size_t rowoff = (size_t)(b * SEQ + kb * 64 + fr) * QKV_N + h * DHEAD + fhf * 32;
        const __half* kr = qh + rowoff + INNER;
        const __half* vr = qh + rowoff + 2 * INNER;
#pragma unroll
        for (int c = 0; c < 4; c++) {
            int cc = (fhf * 4 + c) ^ fsw;
            uint32_t off = (uint32_t)((stage * 512 + fr * 8 + cc) * 16);
            cp_async16(kBase + off, kr + c * 8);
            cp_async16(vBase + off, vr + c * 8);
        }
        asm volatile("cp.async.commit_group;");
    };

    constexpr int NB = SEQ / 64;
    fill(0, 0);
    fill(1, 1);

    for (int kb = 0; kb < NB; kb++) {
        const int stage = kb % 3;
        if (kb + 1 < NB) {
            asm volatile("cp.async.wait_group 1;");
        } else {
            asm volatile("cp.async.wait_group 0;");
        }
        __syncthreads();
        if (kb + 2 < NB) fill(kb + 2, (kb + 2) % 3);

        uint32_t S[2][8][2];
#pragma unroll
        for (int u = 0; u < 2; u++)
#pragma unroll
            for (int j = 0; j < 8; j++) { S[u][j][0] = 0u; S[u][j][1] = 0u; }

#pragma unroll
        for (int kt = 0; kt < 4; kt++) {
            uint32_t Bh[8][2];
#pragma unroll
            for (int jp = 0; jp < 4; jp++) {
                int row = jp * 16 + kRowOff;
                uint32_t off = (uint32_t)((stage * 512 + row * 8 +
                                           ((2 * kt + kHalf) ^ (row & 7))) * 16);
                ldsm_x4(Bh[2 * jp][0], Bh[2 * jp][1], Bh[2 * jp + 1][0], Bh[2 * jp + 1][1],
                        kBase + off);
            }
#pragma unroll
            for (int j = 0; j < 8; j++) {
                mma_f16acc(S[0][j][0], S[0][j][1], Qh[0][kt], Bh[j]);
                mma_f16acc(S[1][j][0], S[1][j][1], Qh[1][kt], Bh[j]);
            }
        }

#pragma unroll
        for (int u = 0; u < 2; u++) {
            __half2 mh0 = __float2half2_rn(-60000.f);
            __half2 mh1 = mh0;
#pragma unroll
            for (int j = 0; j < 8; j++) {
                mh0 = __hmax2(mh0, *reinterpret_cast<__half2*>(&S[u][j][0]));
                mh1 = __hmax2(mh1, *reinterpret_cast<__half2*>(&S[u][j][1]));
            }
            float mx0 = fmaxf(__low2float(mh0), __high2float(mh0));
            float mx1 = fmaxf(__low2float(mh1), __high2float(mh1));
            mx0 = fmaxf(mx0, __shfl_xor_sync(0xffffffffu, mx0, 1));
            mx0 = fmaxf(mx0, __shfl_xor_sync(0xffffffffu, mx0, 2));
            mx1 = fmaxf(mx1, __shfl_xor_sync(0xffffffffu, mx1, 1));
            mx1 = fmaxf(mx1, __shfl_xor_sync(0xffffffffu, mx1, 2));
            float mn0 = fmaxf(m[u][0], mx0);
            float mn1 = fmaxf(m[u][1], mx1);
            float a0 = ex2((m[u][0] - mn0) * CL);
            float a1 = ex2((m[u][1] - mn1) * CL);
            m[u][0] = mn0; m[u][1] = mn1;

            __half2 nm0 = __float2half2_rn(mn0);
            __half2 nm1 = __float2half2_rn(mn1);
            __half2 sum0 = __float2half2_rn(0.f);
            __half2 sum1 = sum0;
#pragma unroll
            for (int j = 0; j < 8; j++) {
                __half2 s0 = *reinterpret_cast<__half2*>(&S[u][j][0]);
                __half2 s1 = *reinterpret_cast<__half2*>(&S[u][j][1]);
                __half2 e0 = h2ex2(__hmul2(__hsub2(s0, nm0), CL2));
                __half2 e1 = h2ex2(__hmul2(__hsub2(s1, nm1), CL2));
                *reinterpret_cast<__half2*>(&S[u][j][0]) = e0;
                *reinterpret_cast<__half2*>(&S[u][j][1]) = e1;
                sum0 = __hadd2(sum0, e0);
                sum1 = __hadd2(sum1, e1);
            }
            float s0 = __low2float(sum0) + __high2float(sum0);
            float s1 = __low2float(sum1) + __high2float(sum1);
            s0 += __shfl_xor_sync(0xffffffffu, s0, 1);
            s0 += __shfl_xor_sync(0xffffffffu, s0, 2);
            s1 += __shfl_xor_sync(0xffffffffu, s1, 1);
            s1 += __shfl_xor_sync(0xffffffffu, s1, 2);
            l[u][0] = l[u][0] * a0 + s0;
            l[u][1] = l[u][1] * a1 + s1;

            __half2 a0h = __float2half2_rn(a0);
            __half2 a1h = __float2half2_rn(a1);
#pragma unroll
            for (int j = 0; j < 8; j++) {
                __half2 o0 = *reinterpret_cast<__half2*>(&O[u][j][0]);
                __half2 o1 = *reinterpret_cast<__half2*>(&O[u][j][1]);
                o0 = __hmul2(o0, a0h);
                o1 = __hmul2(o1, a1h);
                *reinterpret_cast<__half2*>(&O[u][j][0]) = o0;
                *reinterpret_cast<__half2*>(&O[u][j][1]) = o1;
            }
        }

#pragma unroll
        for (int kt = 0; kt < 4; kt++) {
            uint32_t Vb[8][2];
#pragma unroll
            for (int j = 0; j < 8; j++) {
                int row = kt * 16 + vRowOff;
                uint32_t off = (uint32_t)((stage * 512 + row * 8 + (j ^ (row & 7))) * 16);
                ldsm_x2t(Vb[j][0], Vb[j][1], vBase + off);
            }
            uint32_t Pa0[4] = { S[0][2 * kt][0], S[0][2 * kt][1],
                                S[0][2 * kt + 1][0], S[0][2 * kt + 1][1] };
            uint32_t Pa1[4] = { S[1][2 * kt][0], S[1][2 * kt][1],
                                S[1][2 * kt + 1][0], S[1][2 * kt + 1][1] };
#pragma unroll
            for (int j = 0; j < 8; j++) {
                mma_f16acc(O[0][j][0], O[0][j][1], Pa0, Vb[j]);
                mma_f16acc(O[1][j][0], O[1][j][1], Pa1, Vb[j]);
            }
        }
    }

#pragma unroll
    for (int u = 0; u < 2; u++) {
        __half2 il0 = __float2half2_rn(1.f / l[u][0]);
        __half2 il1 = __float2half2_rn(1.f / l[u][1]);
        int row0 = b * SEQ + q0 + warp * 32 + u * 16 + g;
#pragma unroll
        for (int j = 0; j < 8; j++) {
            int col = h * DHEAD + j * 8 + 2 * t;
            __half2 o0 = __hmul2(*reinterpret_cast<__half2*>(&O[u][j][0]), il0);
            __half2 o1 = __hmul2(*reinterpret_cast<__half2*>(&O[u][j][1]), il1);
            *(__half2*)(outH + (size_t)row0 * INNER + col)       = o0;
            *(__half2*)(outH + (size_t)(row0 + 8) * INNER + col) = o1;
        }
    }
}

// ---------------------------------------------------------------------------
// Fused residual + LayerNorm: out = LN(A + B (+ B2)) (+ optional fp16 out)
// ---------------------------------------------------------------------------
__global__ __launch_bounds__(128) void ln_res_kernel(
    const float* __restrict__ A, const float* __restrict__ B,
    const float* __restrict__ B2,
    const float* __restrict__ g, const float* __restrict__ be,
    float* __restrict__ out, __half* __restrict__ outH)
{
    const int row = blockIdx.x;
    const int tid = threadIdx.x;
    const size_t off = (size_t)row * INNER + tid * 4;

    float4 va = *(const float4*)(A + off);
    float4 vb = *(const float4*)(B + off);
    float x0 = va.x + vb.x, x1 = va.y + vb.y, x2 = va.z + vb.z, x3 = va.w + vb.w;
    if (B2) {
        float4 vc = *(const float4*)(B2 + off);
        x0 += vc.x; x1 += vc.y; x2 += vc.z; x3 += vc.w;
    }

    float s  = x0 + x1 + x2 + x3;
    float s2 = x0 * x0 + x1 * x1 + x2 * x2 + x3 * x3;
#pragma unroll
    for (int o2 = 16; o2 >= 1; o2 >>= 1) {
        s  += __shfl_xor_sync(0xffffffffu, s,  o2);
        s2 += __shfl_xor_sync(0xffffffffu, s2, o2);
    }
    __shared__ float sh[8];
    int w = tid >> 5;
    if ((tid & 31) == 0) { sh[w] = s; sh[4 + w] = s2; }
    __syncthreads();
    s  = sh[0] + sh[1] + sh[2] + sh[3];
    s2 = sh[4] + sh[5] + sh[6] + sh[7];

    const float inv_n = 1.f / (float)INNER;
    float mu   = s * inv_n;
    float var  = s2 * inv_n - mu * mu;
    float rstd = rsqrtf(var + LN_EPS);

    float4 vg  = *(const float4*)(g  + tid * 4);
    float4 vbe = *(const float4*)(be + tid * 4);
    float4 vo;
    vo.x = (x0 - mu) * rstd * vg.x + vbe.x;
    vo.y = (x1 - mu) * rstd * vg.y + vbe.y;
    vo.z = (x2 - mu) * rstd * vg.z + vbe.z;
    vo.w = (x3 - mu) * rstd * vg.w + vbe.w;
    *(float4*)(out + off) = vo;

    if (outH) {
        *(uint2*)(outH + off) = make_uint2(packh2(vo.x, vo.y), packh2(vo.z, vo.w));
    }
}

// ---------------------------------------------------------------------------
// Launch
// ---------------------------------------------------------------------------
#define GEMM_SMEM 49152

extern "C" void kernel_launch(void* const* d_in, const int* in_sizes, int n_in,
                              void* d_out, int out_size)
{
    const float* x     = (const float*)d_in[0];
    const float* w_qkv = (const float*)d_in[1];
    const float* w_out = (const float*)d_in[2];
    const float* b_out = (const float*)d_in[3];
    const float* w_ff1 = (const float*)d_in[4];
    const float* w_ff2 = (const float*)d_in[5];
    const float* g1    = (const float*)d_in[6];
    const float* be1   = (const float*)d_in[7];
    const float* g2    = (const float*)d_in[8];
    const float* be2   = (const float*)d_in[9];
    float* out = (float*)d_out;

    float *proj, *projB, *res1, *ff, *ffB;
    __half *ah, *ah2, *bh, *bh2, *wq, *wo;
    cudaGetSymbolAddress((void**)&proj,  g_proj);
    cudaGetSymbolAddress((void**)&projB, g_projB);
    cudaGetSymbolAddress((void**)&res1,  g_res1);
    cudaGetSymbolAddress((void**)&ff,    g_ff);
    cudaGetSymbolAddress((void**)&ffB,   g_ffB);
    cudaGetSymbolAddress((void**)&ah,    g_ah);
    cudaGetSymbolAddress((void**)&ah2,   g_ah2);
    cudaGetSymbolAddress((void**)&bh,    g_bh);
    cudaGetSymbolAddress((void**)&bh2,   g_bh2);
    cudaGetSymbolAddress((void**)&wq,    g_wq);
    cudaGetSymbolAddress((void**)&wo,    g_wo);

    cudaFuncSetAttribute(hgemm_kernel,
                         cudaFuncAttributeMaxDynamicSharedMemorySize, GEMM_SMEM);
    cudaFuncSetAttribute(hgemm16_kernel,
                         cudaFuncAttributeMaxDynamicSharedMemorySize, GEMM_SMEM);

    // 0) all fp16 conversions in one launch
    {
        int n0 = ROWS * INNER / 4, n1 = INNER * QKV_N / 4, n2 = INNER * INNER / 4;
        int n3 = INNER * FF_N / 4, n4 = FF_N * INNER / 4;
        int tot = n0 + n1 + n2 + n3 + n4;
        cvt_h5_kernel<<<(tot + 255) / 256, 256>>>(
            (const float4*)x, (uint2*)ah, n0,
            (const float4*)w_qkv, (uint2*)wq, n1,
            (const float4*)w_out, (uint2*)wo, n2,
            (const float4*)w_ff1, (uint2*)bh, n3,
            (const float4*)w_ff2, (uint2*)bh2, n4);
    }

    // 1) qkv = x @ w_qkv  (fp16 accum, 2x rate -> fp16 out)
    hgemm16_kernel<<<dim3(QKV_N / 128, ROWS / 128), 256, GEMM_SMEM>>>(
        ah, wq, ah2, ROWS, QKV_N, INNER);

    // 2) attention -> fp16 attn out (R13 config)
    attn_mma_kernel<<<dim3(SEQ / 128, BATCH * HEADS), 128>>>(ah2, ah);

    // 3) proj = attn @ w_out + b_out  (split-K=2 -> proj + projB, fp32)
    hgemm_kernel<<<dim3(INNER / 128, ROWS / 128, 2), 256, GEMM_SMEM>>>(
        ah, wo, b_out, proj, projB, nullptr, ROWS, INNER, INNER / 2, INNER);

    // 4) res1 = LN(x + proj + projB), emit fp16
    ln_res_kernel<<<ROWS, 128>>>(x, proj, projB, g1, be1, res1, ah);

    // 5) mid = res1 @ w_ff1 -> fp16
    hgemm_kernel<<<dim3(FF_N / 128, ROWS / 128, 1), 256, GEMM_SMEM>>>(
        ah, bh, nullptr, nullptr, nullptr, ah2, ROWS, FF_N, INNER, INNER);

    // 6) ff = mid @ w_ff2 (split-K=2 -> ff + ffB, fp32)
    hgemm_kernel<<<dim3(INNER / 128, ROWS / 128, 2), 256, GEMM_SMEM>>>(
        ah2, bh2, nullptr, ff, ffB, nullptr, ROWS, INNER, FF_N / 2, FF_N);

    // 7) out = LN(res1 + ff + ffB)
    ln_res_kernel<<<ROWS, 128>>>(res1, ff, ffB, g2, be2, out, nullptr);
}